// round 4
// baseline (speedup 1.0000x reference)
#include <cuda_runtime.h>
#include <math.h>

#define B 512
#define D 256
#define HH 32
#define WW 32
#define TINV 10.0f  // 1/TEMPERATURE

// ---------------- scratch (no allocations allowed) ----------------
__device__ float g_d1[B * D];
__device__ float g_d2[B * D];
__device__ float g_n1[B];
__device__ float g_n2[B];
__device__ float g_p0[B * B];   // split-K partial 0 (raw dot products)
__device__ float g_p1[B * B];   // split-K partial 1
__device__ float g_sim[B * B];
__device__ float g_rowmax[B];
__device__ float g_colmax[B];
__device__ float g_rowden[B];
__device__ float g_colden[B];

// ---------------- kernel 1: masked avg-pool descriptors + norms ----------------
// grid (B, 2), block 256 (8 warps). Warp w owns channels [32w, 32w+32).
// Lane layout: c_off = lane>>3 (4 channel offsets), x4 = lane&7 (8 float4 slots
// covering the 32-pixel row). One LDG.128 covers 4 channels worth of row data;
// 8 per y-iteration cover all 32 channels of the warp. Mask via 0/1 weights.
__global__ void desc_kernel(const float* __restrict__ f1,
                            const float* __restrict__ f2,
                            const float* __restrict__ bb1,
                            const float* __restrict__ bb2) {
    const int b = blockIdx.x;
    const int which = blockIdx.y;
    const float* __restrict__ src = which ? f2 : f1;
    const float* __restrict__ box = which ? bb2 : bb1;
    float* __restrict__ gd = which ? g_d2 : g_d1;
    float* __restrict__ gn = which ? g_n2 : g_n1;

    const int tid = threadIdx.x;
    const int lane = tid & 31;
    const int warp = tid >> 5;
    const int c_off = lane >> 3;  // 0..3
    const int x4 = lane & 7;      // 0..7

    const float x0 = box[b * 4 + 0];
    const float y0 = box[b * 4 + 1];
    const float x1 = box[b * 4 + 2];
    const float y1 = box[b * 4 + 3];

    // per-lane pixel weights for its 4 x-positions (exact reference fp ops)
    float w[4];
#pragma unroll
    for (int j = 0; j < 4; j++) {
        const float xc = ((float)(x4 * 4 + j) + 0.5f) / 32.0f;
        w[j] = (xc >= x0 && xc <= x1) ? 1.0f : 0.0f;
    }
    const bool any = (w[0] + w[1] + w[2] + w[3]) > 0.0f;

    // nx: count active pixels (uniform loop)
    int nx = 0;
#pragma unroll
    for (int x = 0; x < 32; x++) {
        const float xc = ((float)x + 0.5f) / 32.0f;
        if (xc >= x0 && xc <= x1) nx++;
    }
    // y range (contiguous)
    int iy0 = 32, iy1 = -1;
#pragma unroll
    for (int y = 0; y < 32; y++) {
        const float yc = ((float)y + 0.5f) / 32.0f;
        if (yc >= y0 && yc <= y1) { if (y < iy0) iy0 = y; iy1 = y; }
    }
    const int ny = (iy1 >= iy0) ? (iy1 - iy0 + 1) : 0;
    int cnt = nx * ny; if (cnt < 1) cnt = 1;
    const float inv_denom = 1.0f / (float)cnt;

    __shared__ float sdesc[D];
    __shared__ float sred[256];

    // base channel for this lane: warp*32 + c_off; g loop adds 4*g channels
    const float* base = src + (size_t)b * D * (HH * WW)
                            + (size_t)(warp * 32 + c_off) * (HH * WW)
                            + x4 * 4;

    float acc[8];
#pragma unroll
    for (int g = 0; g < 8; g++) acc[g] = 0.f;

    for (int y = iy0; y <= iy1; y++) {
        const float* row = base + y * WW;
        if (any) {
#pragma unroll
            for (int g = 0; g < 8; g++) {
                const float4 v = *(const float4*)(row + (size_t)g * 4 * (HH * WW));
                acc[g] += v.x * w[0] + v.y * w[1] + v.z * w[2] + v.w * w[3];
            }
        }
    }
    // reduce over x4 (8-lane groups: xor 1,2,4)
#pragma unroll
    for (int g = 0; g < 8; g++) {
        acc[g] += __shfl_xor_sync(0xffffffffu, acc[g], 1);
        acc[g] += __shfl_xor_sync(0xffffffffu, acc[g], 2);
        acc[g] += __shfl_xor_sync(0xffffffffu, acc[g], 4);
    }
    if (x4 == 0) {
#pragma unroll
        for (int g = 0; g < 8; g++)
            sdesc[warp * 32 + g * 4 + c_off] = acc[g] * inv_denom;
    }
    __syncthreads();

    const float v = sdesc[tid];
    gd[b * D + tid] = v;

    sred[tid] = v * v;
    __syncthreads();
    for (int s = 128; s; s >>= 1) {
        if (tid < s) sred[tid] += sred[tid + s];
        __syncthreads();
    }
    if (tid == 0) gn[b] = sqrtf(sred[0]);
}

// ---------------- kernel 2: split-K GEMM, raw partials ----------------
// grid (8, 8, 2), block 256. 64x64 tile, 4x4 microtile, K-half = 128 per z.
__global__ void simk_kernel() {
    __shared__ float As[64][68];
    __shared__ float Bs[64][68];

    const int tx = threadIdx.x & 15;
    const int ty = threadIdx.x >> 4;
    const int i0 = blockIdx.y * 64;
    const int j0 = blockIdx.x * 64;
    const int kt0 = blockIdx.z * 128;
    float* __restrict__ out = blockIdx.z ? g_p1 : g_p0;

    float acc[4][4];
#pragma unroll
    for (int r = 0; r < 4; r++)
#pragma unroll
        for (int c = 0; c < 4; c++) acc[r][c] = 0.f;

    for (int kt = kt0; kt < kt0 + 128; kt += 64) {
        for (int l = threadIdx.x; l < 64 * 64; l += 256) {
            const int kk = l & 63;
            const int row = l >> 6;
            As[kk][row] = g_d1[(i0 + row) * D + kt + kk];
            Bs[kk][row] = g_d2[(j0 + row) * D + kt + kk];
        }
        __syncthreads();
#pragma unroll 8
        for (int kk = 0; kk < 64; kk++) {
            float4 a = *(const float4*)&As[kk][ty * 4];
            float4 bv = *(const float4*)&Bs[kk][tx * 4];
            float av[4] = {a.x, a.y, a.z, a.w};
            float bw[4] = {bv.x, bv.y, bv.z, bv.w};
#pragma unroll
            for (int r = 0; r < 4; r++)
#pragma unroll
                for (int c = 0; c < 4; c++) acc[r][c] += av[r] * bw[c];
        }
        __syncthreads();
    }

#pragma unroll
    for (int r = 0; r < 4; r++)
#pragma unroll
        for (int c = 0; c < 4; c++)
            out[(i0 + ty * 4 + r) * B + j0 + tx * 4 + c] = acc[r][c];
}

__device__ __forceinline__ float sim_at(int i, int j) {
    return (g_p0[i * B + j] + g_p1[i * B + j]) /
           fmaxf(g_n1[i] * g_n2[j], 1e-8f);
}

// ---------------- kernel 3: fused combine + maxes (all coalesced) ----------------
// mode 0 (512 blocks): row i — materialize g_sim row, colmax[i] = max(pos, row max)
// mode 1 (16 blocks): column tile of 32 j — rowmax[j] = max(pos, col max)
__global__ void maxfuse_kernel() {
    const int mode = blockIdx.y;
    const int tid = threadIdx.x;
    if (mode == 0) {
        const int i = blockIdx.x;
        const float ni = g_n1[i];
        float m = -INFINITY;
        for (int j = tid; j < B; j += 256) {
            const float s = (g_p0[i * B + j] + g_p1[i * B + j]) /
                            fmaxf(ni * g_n2[j], 1e-8f);
            g_sim[i * B + j] = s;
            if (j != i) m = fmaxf(m, s * TINV);
        }
        __shared__ float sm[256];
        sm[tid] = m;
        __syncthreads();
        for (int s = 128; s; s >>= 1) {
            if (tid < s) sm[tid] = fmaxf(sm[tid], sm[tid + s]);
            __syncthreads();
        }
        if (tid == 0) {
            const float pos = sim_at(i, i) * TINV;
            g_colmax[i] = fmaxf(pos, sm[0]);
        }
    } else {
        if (blockIdx.x >= 16) return;
        const int j = blockIdx.x * 32 + (tid & 31);
        const int yl = tid >> 5;  // 0..7
        const float nj = g_n2[j];
        float m = -INFINITY;
        for (int i = yl; i < B; i += 8) {
            const float s = (g_p0[i * B + j] + g_p1[i * B + j]) /
                            fmaxf(g_n1[i] * nj, 1e-8f);
            if (i != j) m = fmaxf(m, s * TINV);
        }
        __shared__ float sm2[8][32];
        sm2[yl][tid & 31] = m;
        __syncthreads();
        if (tid < 32) {
            float mm = sm2[0][tid];
#pragma unroll
            for (int r = 1; r < 8; r++) mm = fmaxf(mm, sm2[r][tid]);
            const int jj = blockIdx.x * 32 + tid;
            const float pos = sim_at(jj, jj) * TINV;
            g_rowmax[jj] = fmaxf(pos, mm);
        }
    }
}

// ---------------- kernel 4: fused denominators (all coalesced) ----------------
// mode 0 (512 blocks): row_den[i] = sum_{j!=i} exp(sim[i,j]*T - rowmax[j]) + exp(pos_i - rowmax[i])
// mode 1 (16 blocks):  col_den[j] = sum_{i!=j} exp(sim[i,j]*T - colmax[j]) + exp(pos_j - colmax[j])
__global__ void denfuse_kernel() {
    const int mode = blockIdx.y;
    const int tid = threadIdx.x;
    if (mode == 0) {
        const int i = blockIdx.x;
        float s = 0.f;
        for (int j = tid; j < B; j += 256)
            if (j != i) s += expf(g_sim[i * B + j] * TINV - g_rowmax[j]);
        __shared__ float sm[256];
        sm[tid] = s;
        __syncthreads();
        for (int st = 128; st; st >>= 1) {
            if (tid < st) sm[tid] += sm[tid + st];
            __syncthreads();
        }
        if (tid == 0) {
            const float pos = g_sim[i * B + i] * TINV;
            g_rowden[i] = sm[0] + expf(pos - g_rowmax[i]);
        }
    } else {
        if (blockIdx.x >= 16) return;
        const int j = blockIdx.x * 32 + (tid & 31);
        const int yl = tid >> 5;
        const float cm = g_colmax[j];
        float s = 0.f;
        for (int i = yl; i < B; i += 8)
            if (i != j) s += expf(g_sim[i * B + j] * TINV - cm);
        __shared__ float sm2[8][32];
        sm2[yl][tid & 31] = s;
        __syncthreads();
        if (tid < 32) {
            float ss = sm2[0][tid];
#pragma unroll
            for (int r = 1; r < 8; r++) ss += sm2[r][tid];
            const int jj = blockIdx.x * 32 + tid;
            const float pos = g_sim[jj * B + jj] * TINV;
            g_colden[jj] = ss + expf(pos - g_colmax[jj]);
        }
    }
}

// ---------------- kernel 5: final loss ----------------
__global__ void loss_kernel(float* __restrict__ out) {
    const int tid = threadIdx.x;  // 512 threads
    __shared__ float sm[B];
    const float pos = g_sim[tid * B + tid] * TINV;
    const float rlog = logf(expf(pos - g_rowmax[tid]) / g_rowden[tid] + 1e-20f);
    const float clog = logf(expf(pos - g_colmax[tid]) / g_colden[tid] + 1e-20f);
    sm[tid] = -rlog - clog;
    __syncthreads();
    for (int s = 256; s; s >>= 1) {
        if (tid < s) sm[tid] += sm[tid + s];
        __syncthreads();
    }
    if (tid == 0) out[0] = sm[0] / (2.0f * (float)B);
}

extern "C" void kernel_launch(void* const* d_in, const int* in_sizes, int n_in,
                              void* d_out, int out_size) {
    const float* f1 = (const float*)d_in[0];
    const float* f2 = (const float*)d_in[1];
    const float* bb1 = (const float*)d_in[2];
    const float* bb2 = (const float*)d_in[3];
    float* out = (float*)d_out;

    desc_kernel<<<dim3(B, 2), 256>>>(f1, f2, bb1, bb2);
    simk_kernel<<<dim3(8, 8, 2), 256>>>();
    maxfuse_kernel<<<dim3(B, 2), 256>>>();
    denfuse_kernel<<<dim3(B, 2), 256>>>();
    loss_kernel<<<1, B>>>(out);
}

// round 5
// speedup vs baseline: 1.2786x; 1.2786x over previous
#include <cuda_runtime.h>
#include <math.h>

#define B 512
#define D 256
#define HH 32
#define WW 32
#define TINV 10.0f  // 1/TEMPERATURE

// ---------------- scratch (no allocations allowed) ----------------
__device__ float g_d1[B * D];
__device__ float g_d2[B * D];
__device__ float g_n1[B];
__device__ float g_n2[B];
__device__ float g_p0[B * B];   // split-K partial 0 (raw dot products)
__device__ float g_p1[B * B];   // split-K partial 1
__device__ float g_sim[B * B];
__device__ float g_simT[B * B];
__device__ float g_rowmax[B];
__device__ float g_colmax[B];
__device__ float g_rowden[B];
__device__ float g_colden[B];

// ---------------- kernel 1: masked avg-pool descriptors + norms ----------------
// (exact R2 version — measured component of the 100.8us run)
// grid (B, 2), block 256. Lane = x pixel (W==32), warp handles 32 channels,
// 8 channels in flight per inner loop for MLP.
__global__ void desc_kernel(const float* __restrict__ f1,
                            const float* __restrict__ f2,
                            const float* __restrict__ bb1,
                            const float* __restrict__ bb2) {
    const int b = blockIdx.x;
    const int which = blockIdx.y;
    const float* __restrict__ src = which ? f2 : f1;
    const float* __restrict__ box = which ? bb2 : bb1;
    float* __restrict__ gd = which ? g_d2 : g_d1;
    float* __restrict__ gn = which ? g_n2 : g_n1;

    const int tid = threadIdx.x;
    const int lane = tid & 31;
    const int warp = tid >> 5;

    const float x0 = box[b * 4 + 0];
    const float y0 = box[b * 4 + 1];
    const float x1 = box[b * 4 + 2];
    const float y1 = box[b * 4 + 3];

    // x mask for this lane (exact same fp ops as reference: (i+0.5)/32)
    const float xc = ((float)lane + 0.5f) / 32.0f;
    const bool inx = (xc >= x0) && (xc <= x1);

    // y range (contiguous)
    int iy0 = 32, iy1 = -1;
#pragma unroll
    for (int y = 0; y < 32; y++) {
        float yc = ((float)y + 0.5f) / 32.0f;
        if (yc >= y0 && yc <= y1) { if (y < iy0) iy0 = y; iy1 = y; }
    }
    const int nx = __popc(__ballot_sync(0xffffffffu, inx));
    const int ny = (iy1 >= iy0) ? (iy1 - iy0 + 1) : 0;
    int cnt = nx * ny; if (cnt < 1) cnt = 1;
    const float inv_denom = 1.0f / (float)cnt;

    __shared__ float sdesc[D];
    __shared__ float sred[256];

    const float* base = src + (size_t)b * D * (HH * WW);

    // warp `warp` handles channels [warp*32, warp*32+32), 8 at a time
    for (int dd = 0; dd < 32; dd += 8) {
        const int d0 = (warp << 5) + dd;
        const float* p = base + (size_t)d0 * (HH * WW) + lane;
        float s0 = 0.f, s1 = 0.f, s2 = 0.f, s3 = 0.f;
        float s4 = 0.f, s5 = 0.f, s6 = 0.f, s7 = 0.f;
        for (int y = iy0; y <= iy1; y++) {
            const float* q = p + y * WW;
            if (inx) {
                s0 += q[0 * 1024]; s1 += q[1 * 1024];
                s2 += q[2 * 1024]; s3 += q[3 * 1024];
                s4 += q[4 * 1024]; s5 += q[5 * 1024];
                s6 += q[6 * 1024]; s7 += q[7 * 1024];
            }
        }
#pragma unroll
        for (int o = 16; o; o >>= 1) {
            s0 += __shfl_xor_sync(0xffffffffu, s0, o);
            s1 += __shfl_xor_sync(0xffffffffu, s1, o);
            s2 += __shfl_xor_sync(0xffffffffu, s2, o);
            s3 += __shfl_xor_sync(0xffffffffu, s3, o);
            s4 += __shfl_xor_sync(0xffffffffu, s4, o);
            s5 += __shfl_xor_sync(0xffffffffu, s5, o);
            s6 += __shfl_xor_sync(0xffffffffu, s6, o);
            s7 += __shfl_xor_sync(0xffffffffu, s7, o);
        }
        if (lane == 0) {
            sdesc[d0 + 0] = s0 * inv_denom;
            sdesc[d0 + 1] = s1 * inv_denom;
            sdesc[d0 + 2] = s2 * inv_denom;
            sdesc[d0 + 3] = s3 * inv_denom;
            sdesc[d0 + 4] = s4 * inv_denom;
            sdesc[d0 + 5] = s5 * inv_denom;
            sdesc[d0 + 6] = s6 * inv_denom;
            sdesc[d0 + 7] = s7 * inv_denom;
        }
    }
    __syncthreads();

    const float v = sdesc[tid];
    gd[b * D + tid] = v;

    sred[tid] = v * v;
    __syncthreads();
    for (int s = 128; s; s >>= 1) {
        if (tid < s) sred[tid] += sred[tid + s];
        __syncthreads();
    }
    if (tid == 0) gn[b] = sqrtf(sred[0]);
}

// ---------------- kernel 2: split-K GEMM, raw partials ----------------
// grid (8, 8, 2), block 256. 64x64 tile, 4x4 microtile, K-half = 128 per z.
__global__ void simk_kernel() {
    __shared__ float As[64][68];
    __shared__ float Bs[64][68];

    const int tx = threadIdx.x & 15;
    const int ty = threadIdx.x >> 4;
    const int i0 = blockIdx.y * 64;
    const int j0 = blockIdx.x * 64;
    const int kt0 = blockIdx.z * 128;
    float* __restrict__ out = blockIdx.z ? g_p1 : g_p0;

    float acc[4][4];
#pragma unroll
    for (int r = 0; r < 4; r++)
#pragma unroll
        for (int c = 0; c < 4; c++) acc[r][c] = 0.f;

    for (int kt = kt0; kt < kt0 + 128; kt += 64) {
        for (int l = threadIdx.x; l < 64 * 64; l += 256) {
            const int kk = l & 63;
            const int row = l >> 6;
            As[kk][row] = g_d1[(i0 + row) * D + kt + kk];
            Bs[kk][row] = g_d2[(j0 + row) * D + kt + kk];
        }
        __syncthreads();
#pragma unroll 8
        for (int kk = 0; kk < 64; kk++) {
            float4 a = *(const float4*)&As[kk][ty * 4];
            float4 bv = *(const float4*)&Bs[kk][tx * 4];
            float av[4] = {a.x, a.y, a.z, a.w};
            float bw[4] = {bv.x, bv.y, bv.z, bv.w};
#pragma unroll
            for (int r = 0; r < 4; r++)
#pragma unroll
                for (int c = 0; c < 4; c++) acc[r][c] += av[r] * bw[c];
        }
        __syncthreads();
    }

#pragma unroll
    for (int r = 0; r < 4; r++)
#pragma unroll
        for (int c = 0; c < 4; c++)
            out[(i0 + ty * 4 + r) * B + j0 + tx * 4 + c] = acc[r][c];
}

// ---------------- kernel 3: combine partials + norms, write sim and simT ----------------
// grid (16, 16), block 256 (32x8). Each block handles a 32x32 tile:
// reads p0+p1 coalesced, writes sim coalesced, transposes via smem,
// writes simT coalesced. Everything stays in L2.
__global__ void combineT_kernel() {
    __shared__ float t[32][33];
    const int tx = threadIdx.x & 31;
    const int ty = threadIdx.x >> 5;  // 0..7
    const int i0 = blockIdx.y * 32;
    const int j0 = blockIdx.x * 32;

    const float nj = g_n2[j0 + tx];
#pragma unroll
    for (int r = 0; r < 4; r++) {
        const int i = i0 + ty + r * 8;
        const int idx = i * B + j0 + tx;
        const float s = (g_p0[idx] + g_p1[idx]) /
                        fmaxf(g_n1[i] * nj, 1e-8f);
        g_sim[idx] = s;
        t[ty + r * 8][tx] = s;
    }
    __syncthreads();
#pragma unroll
    for (int r = 0; r < 4; r++) {
        const int j = j0 + ty + r * 8;
        g_simT[j * B + i0 + tx] = t[tx][ty + r * 8];
    }
}

// ---------------- kernel 4: maxes — pure row passes, 512-way parallel ----------------
// grid (B, 2), block 256.
// mode 0: colmax[i] = max(pos_i, max_{j!=i} sim[i,j]*T)   (row of sim)
// mode 1: rowmax[j] = max(pos_j, max_{i!=j} simT[j,i]*T)  (row of simT)
__global__ void max_kernel() {
    const int idx = blockIdx.x;
    const int mode = blockIdx.y;
    const int tid = threadIdx.x;
    const float* __restrict__ rowp = (mode ? g_simT : g_sim) + idx * B;
    float m = -INFINITY;
#pragma unroll
    for (int k = 0; k < 2; k++) {
        const int j = tid + k * 256;
        if (j != idx) m = fmaxf(m, rowp[j] * TINV);
    }
    __shared__ float sm[256];
    sm[tid] = m;
    __syncthreads();
    for (int s = 128; s; s >>= 1) {
        if (tid < s) sm[tid] = fmaxf(sm[tid], sm[tid + s]);
        __syncthreads();
    }
    if (tid == 0) {
        const float pos = rowp[idx] * TINV;
        const float mm = fmaxf(pos, sm[0]);
        if (mode == 0) g_colmax[idx] = mm; else g_rowmax[idx] = mm;
    }
}

// ---------------- kernel 5: denominators — pure row passes ----------------
// mode 0: row_den[i] = sum_{j!=i} exp(sim[i,j]*T - rowmax[j]) + exp(pos_i - rowmax[i])
//         (rowmax[j] varies — coalesced vector read)
// mode 1: col_den[j] = sum_{i!=j} exp(simT[j,i]*T - colmax[j]) + exp(pos_j - colmax[j])
//         (colmax[j] fixed)
__global__ void den_kernel() {
    const int idx = blockIdx.x;
    const int mode = blockIdx.y;
    const int tid = threadIdx.x;
    const float* __restrict__ rowp = (mode ? g_simT : g_sim) + idx * B;
    float s = 0.f;
    if (mode == 0) {
#pragma unroll
        for (int k = 0; k < 2; k++) {
            const int j = tid + k * 256;
            if (j != idx) s += expf(rowp[j] * TINV - g_rowmax[j]);
        }
    } else {
        const float cm = g_colmax[idx];
#pragma unroll
        for (int k = 0; k < 2; k++) {
            const int i = tid + k * 256;
            if (i != idx) s += expf(rowp[i] * TINV - cm);
        }
    }
    __shared__ float sm[256];
    sm[tid] = s;
    __syncthreads();
    for (int st = 128; st; st >>= 1) {
        if (tid < st) sm[tid] += sm[tid + st];
        __syncthreads();
    }
    if (tid == 0) {
        const float pos = rowp[idx] * TINV;
        if (mode == 0) g_rowden[idx] = sm[0] + expf(pos - g_rowmax[idx]);
        else           g_colden[idx] = sm[0] + expf(pos - g_colmax[idx]);
    }
}

// ---------------- kernel 6: final loss ----------------
__global__ void loss_kernel(float* __restrict__ out) {
    const int tid = threadIdx.x;  // 512 threads
    __shared__ float sm[B];
    const float pos = g_sim[tid * B + tid] * TINV;
    const float rlog = logf(expf(pos - g_rowmax[tid]) / g_rowden[tid] + 1e-20f);
    const float clog = logf(expf(pos - g_colmax[tid]) / g_colden[tid] + 1e-20f);
    sm[tid] = -rlog - clog;
    __syncthreads();
    for (int s = 256; s; s >>= 1) {
        if (tid < s) sm[tid] += sm[tid + s];
        __syncthreads();
    }
    if (tid == 0) out[0] = sm[0] / (2.0f * (float)B);
}

extern "C" void kernel_launch(void* const* d_in, const int* in_sizes, int n_in,
                              void* d_out, int out_size) {
    const float* f1 = (const float*)d_in[0];
    const float* f2 = (const float*)d_in[1];
    const float* bb1 = (const float*)d_in[2];
    const float* bb2 = (const float*)d_in[3];
    float* out = (float*)d_out;

    desc_kernel<<<dim3(B, 2), 256>>>(f1, f2, bb1, bb2);
    simk_kernel<<<dim3(8, 8, 2), 256>>>();
    combineT_kernel<<<dim3(16, 16), 256>>>();
    max_kernel<<<dim3(B, 2), 256>>>();
    den_kernel<<<dim3(B, 2), 256>>>();
    loss_kernel<<<1, B>>>(out);
}